// round 11
// baseline (speedup 1.0000x reference)
#include <cuda_runtime.h>
#include <cstdint>

// CategoryAdder: out[b,s,:] = inputs[b,s,:] + emb
//   emb = table[categories[b,s]]  if categories[b,s] != 0 AND s != mask_positions[b]
//         0                       otherwise
// B=64, S=2048, D=512. categories/mask_positions int32 on device.
//
// R10 (resubmit; prior round was an infra failure): persistent grid-stride
// variant of the converged R4 body. grid = 148*8 CTAs x 256 thr; each CTA
// loops over 1024-float4 chunks with fully front-batched loads. Removes CTA
// launch/retire churn; loads of iteration i+1 overlap stores of iteration i.

static constexpr int D4 = 128;                                   // float4 per row
static constexpr long long NVEC = (long long)64 * 2048 * D4;     // 16,777,216
static constexpr int THREADS = 256;
static constexpr int VPT = 4;                                    // float4 per thread per iter
static constexpr int CHUNK = THREADS * VPT;                      // 1024 float4 per CTA-iter
static constexpr long long NCHUNK = NVEC / CHUNK;                // 16384
static constexpr unsigned NBLK = 148 * 8;                        // persistent grid

__global__ __launch_bounds__(THREADS)
void category_adder_kernel(const float4* __restrict__ in,
                           const int* __restrict__ cat,
                           const int* __restrict__ mask_pos,
                           const float4* __restrict__ table,
                           float4* __restrict__ out)
{
    for (long long chunk = blockIdx.x; chunk < NCHUNK; chunk += NBLK) {
        const long long base = chunk * CHUNK + threadIdx.x;

        long long idx[VPT];
        long long trow[VPT];
        bool add[VPT];
        float4 v[VPT];

        // Front-batch index math + scalar category/mask loads (L1-hit broadcasts)
        #pragma unroll
        for (int k = 0; k < VPT; k++) {
            idx[k] = base + (long long)k * THREADS;
            long long row = idx[k] >> 7;          // / D4
            int col = (int)(idx[k] & 127);
            int b  = (int)(row >> 11);            // / S
            int s  = (int)(row & 2047);           // % S
            int c  = __ldg(&cat[row]);
            int mp = __ldg(&mask_pos[b]);
            add[k] = (c != 0) && (s != mp);
            trow[k] = (long long)c * D4 + col;
        }

        // Front-batch 4 streaming input loads (evict-first: read-once data)
        #pragma unroll
        for (int k = 0; k < VPT; k++)
            v[k] = __ldcs(&in[idx[k]]);

        // Table gathers (L2-resident) + add
        #pragma unroll
        for (int k = 0; k < VPT; k++) {
            if (add[k]) {
                float4 e = __ldg(&table[trow[k]]);
                v[k].x += e.x; v[k].y += e.y; v[k].z += e.z; v[k].w += e.w;
            }
        }

        // Streaming stores (write-once); next iteration's loads overlap these
        #pragma unroll
        for (int k = 0; k < VPT; k++)
            __stcs(&out[idx[k]], v[k]);
    }
}

extern "C" void kernel_launch(void* const* d_in, const int* in_sizes, int n_in,
                              void* d_out, int out_size)
{
    const float4* inputs  = (const float4*)d_in[0];
    const int*    cats    = (const int*)d_in[1];
    const int*    maskpos = (const int*)d_in[2];
    const float4* table   = (const float4*)d_in[3];
    float4*       out     = (float4*)d_out;

    category_adder_kernel<<<NBLK, THREADS>>>(inputs, cats, maskpos, table, out);
}

// round 13
// speedup vs baseline: 1.1493x; 1.1493x over previous
#include <cuda_runtime.h>
#include <cstdint>

// CategoryAdder: out[b,s,:] = inputs[b,s,:] + emb
//   emb = table[categories[b,s]]  if categories[b,s] != 0 AND s != mask_positions[b]
//         0                       otherwise
// B=64, S=2048, D=512, N_CAT=5000. categories/mask_positions are int32 on device.
//
// FINAL (== R4, best measured: 84.0us, 6.28TB/s HBM = empirical mixed-stream
// ceiling). 4 float4 per thread, block-strided, front-batched loads (MLP=4),
// streaming cache hints on the 512MB in/out stream, table kept L2-resident.
// Seven structural variants (MLP 1/4/8, TMA staging, 256-bit ld/st, 512-thr
// CTAs, persistent grid) bracket this design; all alternatives were <= equal
// or worse. DRAM-ceiling-bound: 512MB compulsory traffic / ~6.3TB/s.

static constexpr int D4 = 128;                                   // float4 per row
static constexpr long long NVEC = (long long)64 * 2048 * D4;     // 16,777,216
static constexpr int THREADS = 256;
static constexpr int VPT = 4;                                    // float4 per thread
static constexpr int BLK_VEC = THREADS * VPT;                    // 1024 float4 / block

__global__ __launch_bounds__(THREADS)
void category_adder_kernel(const float4* __restrict__ in,
                           const int* __restrict__ cat,
                           const int* __restrict__ mask_pos,
                           const float4* __restrict__ table,
                           float4* __restrict__ out)
{
    const long long base = (long long)blockIdx.x * BLK_VEC + threadIdx.x;

    long long idx[VPT];
    long long trow[VPT];
    bool add[VPT];
    float4 v[VPT];

    // Front-batch index math + scalar category/mask loads (L1-hit broadcasts)
    #pragma unroll
    for (int k = 0; k < VPT; k++) {
        idx[k] = base + (long long)k * THREADS;
        long long row = idx[k] >> 7;          // / D4
        int col = (int)(idx[k] & 127);
        int b  = (int)(row >> 11);            // / S
        int s  = (int)(row & 2047);           // % S
        int c  = __ldg(&cat[row]);
        int mp = __ldg(&mask_pos[b]);
        add[k] = (c != 0) && (s != mp);
        trow[k] = (long long)c * D4 + col;
    }

    // Front-batch 4 streaming input loads (evict-first: read-once data)
    #pragma unroll
    for (int k = 0; k < VPT; k++)
        v[k] = __ldcs(&in[idx[k]]);

    // Table gathers (L2-resident) + add
    #pragma unroll
    for (int k = 0; k < VPT; k++) {
        if (add[k]) {
            float4 e = __ldg(&table[trow[k]]);
            v[k].x += e.x; v[k].y += e.y; v[k].z += e.z; v[k].w += e.w;
        }
    }

    // Streaming stores (write-once)
    #pragma unroll
    for (int k = 0; k < VPT; k++)
        __stcs(&out[idx[k]], v[k]);
}

extern "C" void kernel_launch(void* const* d_in, const int* in_sizes, int n_in,
                              void* d_out, int out_size)
{
    const float4* inputs  = (const float4*)d_in[0];
    const int*    cats    = (const int*)d_in[1];
    const int*    maskpos = (const int*)d_in[2];
    const float4* table   = (const float4*)d_in[3];
    float4*       out     = (float4*)d_out;

    const unsigned nblk = (unsigned)(NVEC / BLK_VEC);   // 16384, exact
    category_adder_kernel<<<nblk, THREADS>>>(inputs, cats, maskpos, table, out);
}